// round 2
// baseline (speedup 1.0000x reference)
#include <cuda_runtime.h>
#include <math.h>

// SpectralCirculantLayer: y = ifft(fft(x) * H) + bias  (plain norm; ortho^2 cancels)
// H[k] = w_real[k] + i*w_imag[k] for k < 1024, else 0.  Per-row circular conv, N=4096.
//
// Implementation: rfft-4096 via c2c-2048 (even/odd packing), spectral multiply on
// bins 0..1023 only (H truncation), inverse pack (one-sided since Y[k]=0 for k>=1024),
// irfft via c2c-2048. Mixed-radix Stockham (8,8,8,4) in padded shared memory.
// Persistent CTAs; per-CTA smem twiddle table built once with sincospif.

#define MPTS 2048
#define NTHREADS 256
#define SBUF 2304   // 2048 + 2048/8 padding

__device__ __forceinline__ int pad(int i) { return i + (i >> 3); }

__device__ __forceinline__ float2 cadd(float2 a, float2 b) { return make_float2(a.x + b.x, a.y + b.y); }
__device__ __forceinline__ float2 csub(float2 a, float2 b) { return make_float2(a.x - b.x, a.y - b.y); }
__device__ __forceinline__ float2 cmul(float2 a, float2 b) {
    return make_float2(fmaf(a.x, b.x, -a.y * b.y), fmaf(a.x, b.y, a.y * b.x));
}
// multiply by DIR*i  (DIR=-1 forward: *(-i); DIR=+1 inverse: *(+i))
template <int DIR>
__device__ __forceinline__ float2 mulJ(float2 a) {
    return (DIR < 0) ? make_float2(a.y, -a.x) : make_float2(-a.y, a.x);
}

template <int DIR>
__device__ __forceinline__ void dft4(float2* v) {
    float2 s0 = cadd(v[0], v[2]), d0 = csub(v[0], v[2]);
    float2 s1 = cadd(v[1], v[3]), d1 = mulJ<DIR>(csub(v[1], v[3]));
    v[0] = cadd(s0, s1);
    v[1] = cadd(d0, d1);
    v[2] = csub(s0, s1);
    v[3] = csub(d0, d1);
}

template <int DIR>
__device__ __forceinline__ void dft8(float2* v) {
    const float HC = 0.70710678118654752f;
    float2 b0 = cadd(v[0], v[4]);
    float2 b1 = cadd(v[1], v[5]);
    float2 b2 = cadd(v[2], v[6]);
    float2 b3 = cadd(v[3], v[7]);
    float2 c0 = csub(v[0], v[4]);
    float2 c1 = cmul(csub(v[1], v[5]), make_float2(HC, DIR * HC));
    float2 c2 = mulJ<DIR>(csub(v[2], v[6]));
    float2 c3 = cmul(csub(v[3], v[7]), make_float2(-HC, DIR * HC));
    {   // DFT4(b) -> X0,X2,X4,X6
        float2 s0 = cadd(b0, b2), d0 = csub(b0, b2);
        float2 s1 = cadd(b1, b3), d1 = mulJ<DIR>(csub(b1, b3));
        v[0] = cadd(s0, s1);
        v[2] = cadd(d0, d1);
        v[4] = csub(s0, s1);
        v[6] = csub(d0, d1);
    }
    {   // DFT4(c) -> X1,X3,X5,X7
        float2 s0 = cadd(c0, c2), d0 = csub(c0, c2);
        float2 s1 = cadd(c1, c3), d1 = mulJ<DIR>(csub(c1, c3));
        v[1] = cadd(s0, s1);
        v[3] = cadd(d0, d1);
        v[5] = csub(s0, s1);
        v[7] = csub(d0, d1);
    }
}

// Stockham radix-8 stage. 256 butterflies, one per thread. NS in {1,8,64}.
template <int DIR, int NS, int LOGNS>
__device__ __forceinline__ void stage8(const float2* __restrict__ in, float2* __restrict__ out,
                                       const float2* __restrict__ tw, int t) {
    float2 v[8];
#pragma unroll
    for (int r = 0; r < 8; r++) v[r] = in[pad(t + (r << 8))];
    if (NS > 1) {
        const int jm = t & (NS - 1);
        const int step = MPTS / (NS << 3);
        float2 w = tw[pad(jm * step)];
        if (DIR > 0) w.y = -w.y;
        float2 wr = w;
        v[1] = cmul(v[1], w);
#pragma unroll
        for (int r = 2; r < 8; r++) {
            wr = cmul(wr, w);
            v[r] = cmul(v[r], wr);
        }
    }
    dft8<DIR>(v);
    const int jm = t & (NS - 1);
    const int jd = t >> LOGNS;
    const int o = (jd << (LOGNS + 3)) + jm;
#pragma unroll
    for (int r = 0; r < 8; r++) out[pad(o + (r << LOGNS))] = v[r];
}

// Final Stockham radix-4 stage, NS = 512: indices are j + 512*r on both sides.
template <int DIR>
__device__ __forceinline__ void stage4(const float2* __restrict__ in, float2* __restrict__ out,
                                       const float2* __restrict__ tw, int t) {
#pragma unroll
    for (int h = 0; h < 2; h++) {
        const int j = t + (h << 8);  // 0..511
        float2 v[4];
#pragma unroll
        for (int r = 0; r < 4; r++) v[r] = in[pad(j + (r << 9))];
        float2 w = tw[pad(j)];  // step = 1
        if (DIR > 0) w.y = -w.y;
        float2 w2 = cmul(w, w);
        v[1] = cmul(v[1], w);
        v[2] = cmul(v[2], w2);
        v[3] = cmul(v[3], cmul(w2, w));
        dft4<DIR>(v);
#pragma unroll
        for (int r = 0; r < 4; r++) out[pad(j + (r << 9))] = v[r];
    }
}

__global__ void __launch_bounds__(NTHREADS, 4)
spectral_circulant_kernel(const float* __restrict__ x, const float* __restrict__ wre,
                          const float* __restrict__ wim, const float* __restrict__ bias,
                          float* __restrict__ out, int nrows) {
    extern __shared__ float2 sm[];
    float2* sA = sm;
    float2* sB = sm + SBUF;
    float2* tw = sm + 2 * SBUF;
    const int t = threadIdx.x;

    // One-time per-CTA twiddle table: tw[m] = e^{-2*pi*i*m/2048}
    for (int m = t; m < MPTS; m += NTHREADS) {
        float s, c;
        sincospif(-(float)m * (1.0f / 1024.0f), &s, &c);
        tw[pad(m)] = make_float2(c, s);
    }
    const float bv = __ldg(bias);
    // C1 = e^{-2*pi*i/4096}
    const float2 C1 = make_float2(0.99999882345170188f, -0.00153398018628476f);
    __syncthreads();

    for (int row = blockIdx.x; row < nrows; row += gridDim.x) {
        const float2* xin = reinterpret_cast<const float2*>(x) + (size_t)row * MPTS;
        float2* yout = reinterpret_cast<float2*>(out) + (size_t)row * MPTS;

        // load: z[j] = x[2j] + i*x[2j+1]
        for (int j = t; j < MPTS; j += NTHREADS) sA[pad(j)] = xin[j];
        __syncthreads();

        // Forward c2c-2048: sA -> sB -> sA -> sB -> sA
        stage8<-1, 1, 0>(sA, sB, tw, t);  __syncthreads();
        stage8<-1, 8, 3>(sB, sA, tw, t);  __syncthreads();
        stage8<-1, 64, 6>(sA, sB, tw, t); __syncthreads();
        stage4<-1>(sB, sA, tw, t);        __syncthreads();

        // Untangle rfft bins k<1024, multiply by H, repack for inverse (one-sided:
        // Y[k]=0 for k>=1024, so Zin[k] = Y[k]*(1 + i e^{i phi})/2 and
        // Zin[2048-k] = conj(Y[k])*(1 - i e^{i phi'})/2;  1/2048 IDFT scale folded in.
        for (int k = t; k < 1024; k += NTHREADS) {
            float2 Zk = sA[pad(k)];
            float2 Zm = sA[pad((MPTS - k) & (MPTS - 1))];
            float2 E = make_float2(0.5f * (Zk.x + Zm.x), 0.5f * (Zk.y - Zm.y));
            float2 O = make_float2(0.5f * (Zk.y + Zm.y), -0.5f * (Zk.x - Zm.x));  // -i*(Zk-conj(Zm))/2
            // wq = e^{-2*pi*i*k/4096}
            float2 wq = tw[pad(k >> 1)];
            if (k & 1) wq = cmul(wq, C1);
            float2 X = cadd(E, cmul(O, wq));
            float2 Hk = make_float2(__ldg(wre + k), __ldg(wim + k));
            float2 Y = cmul(X, Hk);
            const float sc = 1.0f / 4096.0f;  // 0.5 (pack) * 1/2048 (IDFT)
            Y.x *= sc;
            Y.y *= sc;
            const float cph = wq.x, sph = -wq.y;  // cos/sin(2 pi k/4096)
            sB[pad(k)] = cmul(Y, make_float2(1.0f - sph, cph));
            if (k > 0) {
                float2 Yc = make_float2(Y.x, -Y.y);
                sB[pad(MPTS - k)] = cmul(Yc, make_float2(1.0f + sph, cph));
            } else {
                sB[pad(1024)] = make_float2(0.0f, 0.0f);
            }
        }
        __syncthreads();

        // Inverse c2c-2048: sB -> sA -> sB -> sA -> sB
        stage8<1, 1, 0>(sB, sA, tw, t);  __syncthreads();
        stage8<1, 8, 3>(sA, sB, tw, t);  __syncthreads();
        stage8<1, 64, 6>(sB, sA, tw, t); __syncthreads();
        stage4<1>(sA, sB, tw, t);        __syncthreads();

        // store: y[2j] = Re z[j] + b, y[2j+1] = Im z[j] + b
        for (int j = t; j < MPTS; j += NTHREADS) {
            float2 z = sB[pad(j)];
            yout[j] = make_float2(z.x + bv, z.y + bv);
        }
        __syncthreads();
    }
}

extern "C" void kernel_launch(void* const* d_in, const int* in_sizes, int n_in,
                              void* d_out, int out_size) {
    const float* x = (const float*)d_in[0];
    const float* wre = (const float*)d_in[1];
    const float* wim = (const float*)d_in[2];
    const float* bias = (const float*)d_in[3];
    float* out = (float*)d_out;

    const int nrows = in_sizes[0] / 4096;  // 8192
    const int smem_bytes = 3 * SBUF * sizeof(float2);  // 55296

    static bool attr_set = false;
    if (!attr_set) {
        cudaFuncSetAttribute(spectral_circulant_kernel,
                             cudaFuncAttributeMaxDynamicSharedMemorySize, smem_bytes);
        attr_set = true;
    }

    const int grid = 608;  // persistent: ~4 CTAs/SM on 152 SMs
    spectral_circulant_kernel<<<grid, NTHREADS, smem_bytes>>>(x, wre, wim, bias, out, nrows);
}

// round 3
// speedup vs baseline: 1.6928x; 1.6928x over previous
#include <cuda_runtime.h>
#include <math.h>

// SpectralCirculantLayer: y = ifft(fft(x) * H) + bias, N=4096 per row, B=8192.
// rfft-4096 via c2c-2048 (even/odd pack), spectral multiply on bins 0..1023 (H
// truncated), one-sided inverse pack, irfft via c2c-2048.
// Radix 16*16*8 Stockham: 3 smem stages per direction, 128 threads per row,
// 2 rows per 256-thread CTA. Global load fused into fwd stage 1, global store
// (+bias) fused into inv stage 3. All twiddles from per-thread register bases
// (row-invariant), no smem twiddle table. H cached in smem.

#define NTHREADS 256
#define SB16 2176   // 2048 + 2048/16 padding

__device__ __forceinline__ int pd(int i) { return i + (i >> 4); }

__device__ __forceinline__ float2 cadd(float2 a, float2 b) { return make_float2(a.x + b.x, a.y + b.y); }
__device__ __forceinline__ float2 csub(float2 a, float2 b) { return make_float2(a.x - b.x, a.y - b.y); }
__device__ __forceinline__ float2 cmul(float2 a, float2 b) {
    return make_float2(fmaf(a.x, b.x, -a.y * b.y), fmaf(a.x, b.y, a.y * b.x));
}
__device__ __forceinline__ float2 conjf2(float2 a) { return make_float2(a.x, -a.y); }

// multiply by DIR*i  (DIR=-1 forward, DIR=+1 inverse)
template <int DIR>
__device__ __forceinline__ float2 mulJ(float2 a) {
    return (DIR < 0) ? make_float2(a.y, -a.x) : make_float2(-a.y, a.x);
}

template <int DIR>
__device__ __forceinline__ void dft4(float2* v) {
    float2 s0 = cadd(v[0], v[2]), d0 = csub(v[0], v[2]);
    float2 s1 = cadd(v[1], v[3]), d1 = mulJ<DIR>(csub(v[1], v[3]));
    v[0] = cadd(s0, s1);
    v[1] = cadd(d0, d1);
    v[2] = csub(s0, s1);
    v[3] = csub(d0, d1);
}

template <int DIR>
__device__ __forceinline__ void dft8(float2* v) {
    const float HC = 0.70710678118654752f;
    float2 b0 = cadd(v[0], v[4]);
    float2 b1 = cadd(v[1], v[5]);
    float2 b2 = cadd(v[2], v[6]);
    float2 b3 = cadd(v[3], v[7]);
    float2 c0 = csub(v[0], v[4]);
    float2 c1 = cmul(csub(v[1], v[5]), make_float2(HC, DIR * HC));
    float2 c2 = mulJ<DIR>(csub(v[2], v[6]));
    float2 c3 = cmul(csub(v[3], v[7]), make_float2(-HC, DIR * HC));
    {
        float2 s0 = cadd(b0, b2), d0 = csub(b0, b2);
        float2 s1 = cadd(b1, b3), d1 = mulJ<DIR>(csub(b1, b3));
        v[0] = cadd(s0, s1);
        v[2] = cadd(d0, d1);
        v[4] = csub(s0, s1);
        v[6] = csub(d0, d1);
    }
    {
        float2 s0 = cadd(c0, c2), d0 = csub(c0, c2);
        float2 s1 = cadd(c1, c3), d1 = mulJ<DIR>(csub(c1, c3));
        v[1] = cadd(s0, s1);
        v[3] = cadd(d0, d1);
        v[5] = csub(s0, s1);
        v[7] = csub(d0, d1);
    }
}

// 16-point DFT in registers: two radix-4 levels (Stockham, self-sorting).
template <int DIR>
__device__ __forceinline__ void dft16(float2* v) {
    const float C1 = 0.92387953251128675f;  // cos(pi/8)
    const float S1 = 0.38268343236508977f;  // sin(pi/8)
    const float H2 = 0.70710678118654752f;
    const float2 W1 = make_float2(C1, DIR * S1);
    const float2 W2 = make_float2(H2, DIR * H2);
    const float2 W3 = make_float2(S1, DIR * C1);
    const float2 W6 = make_float2(-H2, DIR * H2);
    const float2 W9 = make_float2(-C1, -DIR * S1);

    float2 u[16];
#pragma unroll
    for (int i = 0; i < 4; i++) {
        float2 a[4] = {v[i], v[i + 4], v[i + 8], v[i + 12]};
        dft4<DIR>(a);
        u[4 * i + 0] = a[0];
        u[4 * i + 1] = a[1];
        u[4 * i + 2] = a[2];
        u[4 * i + 3] = a[3];
    }
    {  // j = 0
        float2 a[4] = {u[0], u[4], u[8], u[12]};
        dft4<DIR>(a);
        v[0] = a[0]; v[4] = a[1]; v[8] = a[2]; v[12] = a[3];
    }
    {  // j = 1: powers 1,2,3
        float2 a[4] = {u[1], cmul(u[5], W1), cmul(u[9], W2), cmul(u[13], W3)};
        dft4<DIR>(a);
        v[1] = a[0]; v[5] = a[1]; v[9] = a[2]; v[13] = a[3];
    }
    {  // j = 2: powers 2,4,6
        float2 a[4] = {u[2], cmul(u[6], W2), mulJ<DIR>(u[10]), cmul(u[14], W6)};
        dft4<DIR>(a);
        v[2] = a[0]; v[6] = a[1]; v[10] = a[2]; v[14] = a[3];
    }
    {  // j = 3: powers 3,6,9
        float2 a[4] = {u[3], cmul(u[7], W3), cmul(u[11], W6), cmul(u[15], W9)};
        dft4<DIR>(a);
        v[3] = a[0]; v[7] = a[1]; v[11] = a[2]; v[15] = a[3];
    }
}

// Stage 1: radix-16, NS=1. tl = 0..127. Reads global (GIN) or padded smem.
template <int DIR, bool GIN>
__device__ __forceinline__ void stage_r16_ns1(const float2* __restrict__ in,
                                              float2* __restrict__ out, int tl) {
    float2 v[16];
#pragma unroll
    for (int r = 0; r < 16; r++) v[r] = GIN ? in[tl + (r << 7)] : in[pd(tl + (r << 7))];
    dft16<DIR>(v);
#pragma unroll
    for (int r = 0; r < 16; r++) out[pd((tl << 4) + r)] = v[r];
}

// Stage 2: radix-16, NS=16. wb = e^{DIR*2pi*i*(tl&15)/256}.
template <int DIR>
__device__ __forceinline__ void stage_r16_ns16(const float2* __restrict__ in,
                                               float2* __restrict__ out, int tl, float2 wb) {
    float2 v[16];
#pragma unroll
    for (int r = 0; r < 16; r++) v[r] = in[pd(tl + (r << 7))];
    float2 wr = wb;
    v[1] = cmul(v[1], wr);
#pragma unroll
    for (int r = 2; r < 16; r++) {
        wr = cmul(wr, wb);
        v[r] = cmul(v[r], wr);
    }
    dft16<DIR>(v);
    const int jm = tl & 15, jd = tl >> 4;
    const int o = (jd << 8) + jm;
#pragma unroll
    for (int r = 0; r < 16; r++) out[pd(o + (r << 4))] = v[r];
}

// Stage 3: radix-8, NS=256. Two butterflies per thread: j = tl and tl+128.
// wA = e^{DIR*2pi*i*tl/2048}, wB = wA * e^{DIR*2pi*i*128/2048}.
// GOUT: write to global with bias add (unpadded, coalesced).
template <int DIR, bool GOUT>
__device__ __forceinline__ void stage_r8_ns256(const float2* __restrict__ in,
                                               float2* __restrict__ out, int tl,
                                               float2 wA, float2 wB, float bv) {
#pragma unroll
    for (int h = 0; h < 2; h++) {
        const int j = tl + (h << 7);
        const float2 wb = h ? wB : wA;
        float2 v[8];
#pragma unroll
        for (int r = 0; r < 8; r++) v[r] = in[pd(j + (r << 8))];
        float2 wr = wb;
        v[1] = cmul(v[1], wr);
#pragma unroll
        for (int r = 2; r < 8; r++) {
            wr = cmul(wr, wb);
            v[r] = cmul(v[r], wr);
        }
        dft8<DIR>(v);
#pragma unroll
        for (int r = 0; r < 8; r++) {
            if (GOUT)
                out[j + (r << 8)] = make_float2(v[r].x + bv, v[r].y + bv);
            else
                out[pd(j + (r << 8))] = v[r];
        }
    }
}

// Untangle rfft, multiply by H, repack one-sided for inverse. wqb = e^{-2pi*i*tl/4096}.
__device__ __forceinline__ void midstage(const float2* __restrict__ S, float2* __restrict__ D,
                                         const float2* __restrict__ Hs, int tl, float2 wqb) {
    // MC[i] = e^{-pi*i*i16/16}, i16 = i
    const float MCC[8] = {1.0f, 0.98078528040323044f, 0.92387953251128675f, 0.83146961230254524f,
                          0.70710678118654752f, 0.55557023301960222f, 0.38268343236508977f, 0.19509032201612827f};
    const float MCS[8] = {0.0f, -0.19509032201612827f, -0.38268343236508977f, -0.55557023301960222f,
                          -0.70710678118654752f, -0.83146961230254524f, -0.92387953251128675f, -0.98078528040323044f};
#pragma unroll
    for (int i = 0; i < 8; i++) {
        const int k = tl + (i << 7);
        const float2 Ci = make_float2(MCC[i], MCS[i]);
        const float2 wq = cmul(wqb, Ci);  // e^{-2pi*i*k/4096}
        float2 Zk = S[pd(k)];
        float2 Zm = S[pd((2048 - k) & 2047)];
        float2 E = make_float2(0.5f * (Zk.x + Zm.x), 0.5f * (Zk.y - Zm.y));
        float2 O = make_float2(0.5f * (Zk.y + Zm.y), -0.5f * (Zk.x - Zm.x));
        float2 Xk = cadd(E, cmul(O, wq));
        float2 Hk = Hs[k];
        float2 Yk = cmul(Xk, Hk);
        const float sc = 1.0f / 4096.0f;  // 0.5 (pack) * 1/2048 (IDFT)
        Yk.x *= sc;
        Yk.y *= sc;
        const float cph = wq.x, sph = -wq.y;
        D[pd(k)] = cmul(Yk, make_float2(1.0f - sph, cph));
        if (k > 0) {
            float2 Yc = make_float2(Yk.x, -Yk.y);
            D[pd(2048 - k)] = cmul(Yc, make_float2(1.0f + sph, cph));
        } else {
            D[pd(1024)] = make_float2(0.0f, 0.0f);
        }
    }
}

__global__ void __launch_bounds__(NTHREADS, 2)
spectral_circulant_kernel(const float* __restrict__ x, const float* __restrict__ wre,
                          const float* __restrict__ wim, const float* __restrict__ bias,
                          float* __restrict__ out, int nrows) {
    extern __shared__ float2 sm[];
    const int t = threadIdx.x;
    const int g = t >> 7, tl = t & 127;
    float2* X = sm + g * (2 * SB16);
    float2* Y = X + SB16;
    float2* Hs = sm + 4 * SB16;  // 1024 float2

    // One-time: cache H in smem
    for (int k = t; k < 1024; k += NTHREADS) Hs[k] = make_float2(__ldg(wre + k), __ldg(wim + k));
    const float bv = __ldg(bias);

    // Per-thread twiddle bases (row-invariant)
    float s, c;
    sincospif(-(float)(tl & 15) * (1.0f / 128.0f), &s, &c);
    const float2 w2f = make_float2(c, s);  // e^{-2pi*i*(tl&15)/256}
    sincospif(-(float)tl * (1.0f / 1024.0f), &s, &c);
    const float2 w3f = make_float2(c, s);  // e^{-2pi*i*tl/2048}
    sincospif(-(float)tl * (1.0f / 2048.0f), &s, &c);
    const float2 wqb = make_float2(c, s);  // e^{-2pi*i*tl/4096}
    // e^{-2pi*i*128/2048} = e^{-pi*i/8}
    const float2 E8 = make_float2(0.92387953251128675f, -0.38268343236508977f);
    const float2 w3g = cmul(w3f, E8);
    const float2 w2i = conjf2(w2f);
    const float2 w3i = conjf2(w3f);
    const float2 w3gi = conjf2(w3g);
    __syncthreads();

    for (int row = blockIdx.x * 2 + g; row < nrows; row += gridDim.x * 2) {
        const float2* xin = reinterpret_cast<const float2*>(x) + (size_t)row * 2048;
        float2* yout = reinterpret_cast<float2*>(out) + (size_t)row * 2048;

        // Forward c2c-2048
        stage_r16_ns1<-1, true>(xin, Y, tl);
        __syncthreads();
        stage_r16_ns16<-1>(Y, X, tl, w2f);
        __syncthreads();
        stage_r8_ns256<-1, false>(X, Y, tl, w3f, w3g, 0.0f);
        __syncthreads();

        midstage(Y, X, Hs, tl, wqb);
        __syncthreads();

        // Inverse c2c-2048 (scale folded into midstage)
        stage_r16_ns1<1, false>(X, Y, tl);
        __syncthreads();
        stage_r16_ns16<1>(Y, X, tl, w2i);
        __syncthreads();
        stage_r8_ns256<1, true>(X, yout, tl, w3i, w3gi, bv);
        // no trailing sync needed: Y next written only after the sync following
        // fwd stage 1, X next written after sync following fwd stage 2.
    }
}

extern "C" void kernel_launch(void* const* d_in, const int* in_sizes, int n_in,
                              void* d_out, int out_size) {
    const float* x = (const float*)d_in[0];
    const float* wre = (const float*)d_in[1];
    const float* wim = (const float*)d_in[2];
    const float* bias = (const float*)d_in[3];
    float* out = (float*)d_out;

    const int nrows = in_sizes[0] / 4096;  // 8192
    const int smem_bytes = (4 * SB16 + 1024) * sizeof(float2);  // 77824

    static int grid = 0;
    if (grid == 0) {
        cudaFuncSetAttribute(spectral_circulant_kernel,
                             cudaFuncAttributeMaxDynamicSharedMemorySize, smem_bytes);
        int nsm = 148;
        cudaDeviceGetAttribute(&nsm, cudaDevAttrMultiProcessorCount, 0);
        grid = 2 * nsm;  // persistent, 2 CTAs/SM (smem-limited)
    }

    spectral_circulant_kernel<<<grid, NTHREADS, smem_bytes>>>(x, wre, wim, bias, out, nrows);
}